// round 15
// baseline (speedup 1.0000x reference)
#include <cuda_runtime.h>
#include <cstdint>

// Problem dims
#define B_    64
#define T_    512
#define THARM 256
#define TSPK  256
#define NI_   64
#define H_    1024

#define DTF      0.042f
#define THRESH   0.008f
#define RESETV   0.001f

// Output layout: concat of hys (B,T,H), hzs (B,T,H), us (B,TSPK,H), spikes (B,TSPK,H)
#define OFF_HZS  33554432   // 64*512*1024
#define OFF_US   67108864
#define OFF_SPK  83886080

#define NSPLIT 16           // K splits of 64
#define NTILES 8            // N tiles of 128
#define GRID   128          // NTILES * NSPLIT

// ---------------- device scratch (static: no allocation) ----------------
__device__ float g_P[THARM * B_ * H_];     // x[:, :256, :] @ x2h   (64 MB)
__device__ float g_hy[2][B_ * H_];         // double-buffered harmonic state
__device__ float g_hz[B_ * H_];
__device__ float g_Wp[NSPLIT][B_ * H_];    // split-K partials (deterministic sum)
__device__ volatile unsigned g_gen;        // grid barrier generation
__device__ unsigned g_count;               // grid barrier arrival count

// ---------------- f32x2 helpers (Blackwell packed fp32) ----------------
__device__ __forceinline__ void fma2(unsigned long long& d,
                                     unsigned long long a, unsigned long long b) {
    asm("fma.rn.f32x2 %0, %1, %2, %0;" : "+l"(d) : "l"(a), "l"(b));
}
__device__ __forceinline__ float2 unpk(unsigned long long u) {
    float2 f;
    asm("mov.b64 {%0, %1}, %2;" : "=f"(f.x), "=f"(f.y) : "l"(u));
    return f;
}

// ---------------- lean grid-wide barrier (128 CTAs, 1 wave) ----------------
__device__ __forceinline__ void grid_sync() {
    __syncthreads();                       // all CTA stores happen-before tid0's fence
    if (threadIdx.x == 0) {
        __threadfence();                   // release (MEMBAR.GL + CCTL.IVALL)
        unsigned gen = g_gen;
        if (atomicAdd(&g_count, 1u) == GRID - 1u) {
            g_count = 0u;                  // reset BEFORE gen flip
            __threadfence();
            g_gen = gen + 1u;
        } else {
            while (g_gen == gen) { __nanosleep(20); }
        }
        __threadfence();                   // acquire + SM-wide L1 invalidation
    }
    __syncthreads();
}

// ---------------- init ----------------
__global__ void init_kernel() {
    int i = blockIdx.x * blockDim.x + threadIdx.x;
    if (i < B_ * H_) {
        g_hy[0][i] = 0.f;
        g_hy[1][i] = 0.f;
        g_hz[i]    = 0.f;
    }
    if (i == 0) { g_count = 0u; g_gen = 0u; }
}

// ---------------- P = x[:, :256, :] @ x2h ----------------
__global__ void p_kernel(const float* __restrict__ x, const float* __restrict__ x2h) {
    const int t  = blockIdx.x;
    const int n0 = blockIdx.y * 64;

    __shared__ __align__(16) float Xs[64 * 68];
    __shared__ __align__(16) float Ws[64 * 68];

    const int tid = threadIdx.x;
#pragma unroll
    for (int i = 0; i < 4; i++) {
        int idx4 = tid + i * 256;
        int b  = idx4 >> 4;
        int k4 = (idx4 & 15) * 4;
        const float4 v = *(const float4*)&x[(b * T_ + t) * NI_ + k4];
        Xs[(k4 + 0) * 68 + b] = v.x;
        Xs[(k4 + 1) * 68 + b] = v.y;
        Xs[(k4 + 2) * 68 + b] = v.z;
        Xs[(k4 + 3) * 68 + b] = v.w;
    }
#pragma unroll
    for (int i = 0; i < 4; i++) {
        int idx4 = tid + i * 256;
        int k  = idx4 >> 4;
        int n4 = (idx4 & 15) * 4;
        *(float4*)&Ws[k * 68 + n4] = *(const float4*)&x2h[k * H_ + n0 + n4];
    }
    __syncthreads();

    const int tx = tid & 15, ty = tid >> 4;
    float acc[4][4] = {};
#pragma unroll
    for (int k = 0; k < 64; k++) {
        const float4 a  = *(const float4*)&Xs[k * 68 + ty * 4];
        const float4 bb = *(const float4*)&Ws[k * 68 + tx * 4];
        acc[0][0] += a.x * bb.x; acc[0][1] += a.x * bb.y; acc[0][2] += a.x * bb.z; acc[0][3] += a.x * bb.w;
        acc[1][0] += a.y * bb.x; acc[1][1] += a.y * bb.y; acc[1][2] += a.y * bb.z; acc[1][3] += a.y * bb.w;
        acc[2][0] += a.z * bb.x; acc[2][1] += a.z * bb.y; acc[2][2] += a.z * bb.z; acc[2][3] += a.z * bb.w;
        acc[3][0] += a.w * bb.x; acc[3][1] += a.w * bb.y; acc[3][2] += a.w * bb.z; acc[3][3] += a.w * bb.w;
    }
#pragma unroll
    for (int i = 0; i < 4; i++) {
        int b = ty * 4 + i;
        *(float4*)&g_P[(t * 64 + b) * H_ + n0 + tx * 4] =
            make_float4(acc[i][0], acc[i][1], acc[i][2], acc[i][3]);
    }
}

// ---------------- persistent harmonic recurrence ----------------
// 128 CTAs: tile = blockIdx.x>>4 (8 N-tiles of 128), split = blockIdx.x&15 (K chunks of 64)
// 512 threads. Dynamic smem: As2 = duplicated A (64 rows x 64 k, 8B dup pairs, 32 KB)
//                            Bs  = h2h slice (64 k x 128 n, 32 KB), loaded once.
// Warp w owns m-rows 4w..4w+3 -> all A-operand LDS are warp-uniform broadcasts.
__global__ void __launch_bounds__(512, 1)
ron_kernel(const float* __restrict__ h2h,
           const float* __restrict__ bias,
           const float* __restrict__ gamma_,
           const float* __restrict__ eps_,
           float* __restrict__ out) {
    extern __shared__ __align__(16) float dsm[];
    float* As2 = dsm;                 // [64][128] : (a,a) pairs, row m at m*128, k pair at k*2
    float* Bs  = dsm + 64 * 128;      // [64][128] : Bs[k*128 + n]

    const int tile  = blockIdx.x >> 4;
    const int split = blockIdx.x & 15;
    const int n0 = tile * 128;
    const int k0 = split * 64;
    const int tid = threadIdx.x;
    const int w    = tid >> 5;        // warp id 0..15 -> m-rows 4w..4w+3
    const int lane = tid & 31;        // -> n cols lane*4..lane*4+3

    // load h2h slice once (reused all 256 steps)
#pragma unroll
    for (int i = 0; i < 4; i++) {
        int idx4 = tid + i * 512;
        int k  = idx4 >> 5;
        int n4 = (idx4 & 31) * 4;
        *(float4*)&Bs[k * 128 + n4] = *(const float4*)&h2h[(k0 + k) * H_ + n0 + n4];
    }

    float* __restrict__ wp = g_Wp[split];

    // update-phase invariants (tid<128 updates one float4; same g every step)
    const int g = (blockIdx.x * 128 + (tid & 127)) * 4;
    const int ub = g >> 10;
    const int uh = g & 1023;
    const float4 bv = *(const float4*)&bias[uh];
    const float4 gv = *(const float4*)&gamma_[uh];
    const float4 ev = *(const float4*)&eps_[uh];

    for (int t = 0; t <= THARM; t++) {
        const float* __restrict__ hy = g_hy[t & 1];

        // fill As2 with duplicated hy[m, k0:k0+64]: thread -> row m = tid>>3, k = (tid&7)*8..+7
        {
            const int m  = tid >> 3;
            const int kq = (tid & 7) * 8;
            const float4 v0 = *(const float4*)&hy[m * H_ + k0 + kq];
            const float4 v1 = *(const float4*)&hy[m * H_ + k0 + kq + 4];
            float* dst = &As2[m * 128 + kq * 2];
            *(float4*)&dst[0]  = make_float4(v0.x, v0.x, v0.y, v0.y);
            *(float4*)&dst[4]  = make_float4(v0.z, v0.z, v0.w, v0.w);
            *(float4*)&dst[8]  = make_float4(v1.x, v1.x, v1.y, v1.y);
            *(float4*)&dst[12] = make_float4(v1.z, v1.z, v1.w, v1.w);
        }
        __syncthreads();

        // GEMM: 64m x 128n x 64k ; thread tile 4m x 4n (2 f32x2 pairs per row)
        unsigned long long acc[4][2] = {};
        const unsigned long long* __restrict__ A0 = (const unsigned long long*)&As2[(w * 4 + 0) * 128];
        const unsigned long long* __restrict__ A1 = (const unsigned long long*)&As2[(w * 4 + 1) * 128];
        const unsigned long long* __restrict__ A2 = (const unsigned long long*)&As2[(w * 4 + 2) * 128];
        const unsigned long long* __restrict__ A3 = (const unsigned long long*)&As2[(w * 4 + 3) * 128];
#pragma unroll 4
        for (int kb = 0; kb < 16; kb++) {
#pragma unroll
            for (int j = 0; j < 4; j++) {
                const int k = kb * 4 + j;
                const ulonglong2 q = *(const ulonglong2*)&Bs[k * 128 + lane * 4];
                const unsigned long long a0 = A0[k];   // broadcast LDS.64, already duplicated
                const unsigned long long a1 = A1[k];
                const unsigned long long a2 = A2[k];
                const unsigned long long a3 = A3[k];
                fma2(acc[0][0], a0, q.x); fma2(acc[0][1], a0, q.y);
                fma2(acc[1][0], a1, q.x); fma2(acc[1][1], a1, q.y);
                fma2(acc[2][0], a2, q.x); fma2(acc[2][1], a2, q.y);
                fma2(acc[3][0], a3, q.x); fma2(acc[3][1], a3, q.y);
            }
        }

        // store split-K partials (fixed slot -> deterministic reduction order)
#pragma unroll
        for (int i = 0; i < 4; i++) {
            const int m = w * 4 + i;
            const float2 p0 = unpk(acc[i][0]), p1 = unpk(acc[i][1]);
            *(float4*)&wp[m * H_ + n0 + lane * 4] = make_float4(p0.x, p0.y, p1.x, p1.y);
        }

        if (t == THARM) break;   // final hyW: partials consumed by spike_kernel

        // preload update operands independent of partials (overlap with barrier wait)
        float4 hyv, hzv, pv;
        if (tid < 128) {
            hyv = *(const float4*)&hy[g];
            hzv = *(const float4*)&g_hz[g];
            pv  = *(const float4*)&g_P[t * (B_ * H_) + g];
        }

        grid_sync();             // all partials of step t visible

        // distributed ODE update: 16384 float4-groups over 128 CTAs x 128 threads
        if (tid < 128) {
            float4 wsum = *(const float4*)&g_Wp[0][g];
#pragma unroll
            for (int s = 1; s < NSPLIT; s++) {
                const float4 ws = *(const float4*)&g_Wp[s][g];
                wsum.x += ws.x; wsum.y += ws.y; wsum.z += ws.z; wsum.w += ws.w;
            }

            float4 hz2, hy2;
            hz2.x = hzv.x + DTF * (tanhf(pv.x + wsum.x + bv.x) - gv.x * hyv.x - ev.x * hzv.x);
            hz2.y = hzv.y + DTF * (tanhf(pv.y + wsum.y + bv.y) - gv.y * hyv.y - ev.y * hzv.y);
            hz2.z = hzv.z + DTF * (tanhf(pv.z + wsum.z + bv.z) - gv.z * hyv.z - ev.z * hzv.z);
            hz2.w = hzv.w + DTF * (tanhf(pv.w + wsum.w + bv.w) - gv.w * hyv.w - ev.w * hzv.w);
            hy2.x = hyv.x + DTF * hz2.x;
            hy2.y = hyv.y + DTF * hz2.y;
            hy2.z = hyv.z + DTF * hz2.z;
            hy2.w = hyv.w + DTF * hz2.w;

            *(float4*)&g_hy[(t & 1) ^ 1][g] = hy2;
            *(float4*)&g_hz[g]              = hz2;

            const int o = (ub * T_ + t) * H_ + uh;
            *(float4*)&out[o]           = hy2;
            *(float4*)&out[OFF_HZS + o] = hz2;
        }

        grid_sync();             // hy[next] ready before next step's As2 fill
    }
}

// ---------------- broadcast tails: hys/hzs[:,256:,:] = final state ----------------
__global__ void tail_kernel(float* __restrict__ out) {
    int idx = blockIdx.x * blockDim.x + threadIdx.x;
    int e = idx * 4;
    int h = e & 1023;
    int t = (e >> 10) & 255;
    int b = e >> 18;
    const float4 hyv = *(const float4*)&g_hy[0][b * H_ + h];
    const float4 hzv = *(const float4*)&g_hz[b * H_ + h];
    const int o = (b * T_ + 256 + t) * H_ + h;
    *(float4*)&out[o]           = hyv;
    *(float4*)&out[OFF_HZS + o] = hzv;
}

// ---------------- spiking phase: per-(b,h) sequential LIF chain ----------------
__global__ void spike_kernel(float* __restrict__ out) {
    const int g = blockIdx.x * blockDim.x + threadIdx.x;
    const int b = g >> 10;
    const int h = g & 1023;

    float hyW = 0.f;
#pragma unroll
    for (int s = 0; s < NSPLIT; s++) hyW += g_Wp[s][g];

    float* __restrict__ us = out + OFF_US;
    float* __restrict__ sp = out + OFF_SPK;
    const float* __restrict__ Pp = g_P + g;
    const int ob = (b * TSPK) * H_ + h;

    float u = 0.f;
#pragma unroll 4
    for (int t = 0; t < TSPK; t++) {
        const float pt = Pp[t * (B_ * H_)];
        const float s = (u > THRESH) ? 1.f : 0.f;
        if (u > THRESH) u = RESETV;
        u = u + ((-u + hyW + pt) * 0.025f) * 0.042f;
        us[ob + t * H_] = u;
        sp[ob + t * H_] = s;
    }
}

// ---------------- launch ----------------
extern "C" void kernel_launch(void* const* d_in, const int* in_sizes, int n_in,
                              void* d_out, int out_size) {
    const float* x    = (const float*)d_in[0];
    const float* x2h  = (const float*)d_in[1];
    const float* h2h  = (const float*)d_in[2];
    const float* bias = (const float*)d_in[3];
    const float* gam  = (const float*)d_in[4];
    const float* eps  = (const float*)d_in[5];
    float* out = (float*)d_out;
    (void)in_sizes; (void)n_in; (void)out_size;

    const int dyn_smem = 64 * 1024;   // As2 32KB + Bs 32KB
    cudaFuncSetAttribute(ron_kernel, cudaFuncAttributeMaxDynamicSharedMemorySize, dyn_smem);

    init_kernel<<<(B_ * H_ + 255) / 256, 256>>>();
    p_kernel<<<dim3(THARM, H_ / 64), 256>>>(x, x2h);
    ron_kernel<<<GRID, 512, dyn_smem>>>(h2h, bias, gam, eps, out);
    tail_kernel<<<(B_ * TSPK * H_ / 4 + 255) / 256, 256>>>(out);
    spike_kernel<<<(B_ * H_ + 255) / 256, 256>>>(out);
}

// round 17
// speedup vs baseline: 1.3418x; 1.3418x over previous
#include <cuda_runtime.h>
#include <cstdint>

// Problem dims
#define B_    64
#define T_    512
#define THARM 256
#define TSPK  256
#define NI_   64
#define H_    1024

#define DTF      0.042f
#define THRESH   0.008f
#define RESETV   0.001f

// Output layout: concat of hys (B,T,H), hzs (B,T,H), us (B,TSPK,H), spikes (B,TSPK,H)
#define OFF_HZS  33554432   // 64*512*1024
#define OFF_US   67108864
#define OFF_SPK  83886080

#define NSPLIT 16           // K splits of 64
#define NTILES 8            // N tiles of 128
#define GRID   128          // NTILES * NSPLIT
#define BH     (B_ * H_)

// ---------------- device scratch (static: no allocation) ----------------
__device__ float g_P[THARM * B_ * H_];        // x[:, :256, :] @ x2h   (64 MB)
__device__ float g_hy[2][B_ * H_];            // double-buffered harmonic state
__device__ float g_hzF[B_ * H_];              // final hz snapshot (tail_kernel)
__device__ float g_Wp[2][NSPLIT][B_ * H_];    // split-K partials, step-parity doubled
__device__ volatile unsigned g_pcnt[NTILES];  // per-tile partials-done counter (16/step)
__device__ volatile unsigned g_scnt[NSPLIT];  // per-split hy-slice-done counter (8/step)

// ---------------- f32x2 helpers (Blackwell packed fp32) ----------------
__device__ __forceinline__ unsigned long long dupf(float v) {
    unsigned long long r;
    unsigned u = __float_as_uint(v);
    asm("mov.b64 %0, {%1, %1};" : "=l"(r) : "r"(u));
    return r;
}
__device__ __forceinline__ void fma2(unsigned long long& d,
                                     unsigned long long a, unsigned long long b) {
    asm("fma.rn.f32x2 %0, %1, %2, %0;" : "+l"(d) : "l"(a), "l"(b));
}
__device__ __forceinline__ float2 unpk(unsigned long long u) {
    float2 f;
    asm("mov.b64 {%0, %1}, %2;" : "=f"(f.x), "=f"(f.y) : "l"(u));
    return f;
}

// ---------------- point-to-point sync primitives (R10-proven pattern) ----------------
// arrive: all CTA threads' prior stores -> bar.sync -> tid0 release fence -> counter++
__device__ __forceinline__ void arrive(volatile unsigned* p) {
    __syncthreads();
    if (threadIdx.x == 0) {
        __threadfence();                       // release (MEMBAR.GL + CCTL.IVALL)
        atomicAdd((unsigned*)p, 1u);
    }
}
// wait: tid0 spins until counter >= target, acquire fence (SM-wide L1 inval), bar.sync
__device__ __forceinline__ void wait_ge(volatile unsigned* p, unsigned target) {
    if (threadIdx.x == 0) {
        while (*p < target) { __nanosleep(20); }
        __threadfence();                       // acquire + L1 invalidation
    }
    __syncthreads();
}

// ---------------- init (runs every graph replay: reset state) ----------------
__global__ void init_kernel() {
    int i = blockIdx.x * blockDim.x + threadIdx.x;
    if (i < B_ * H_) {
        g_hy[0][i] = 0.f;
        g_hy[1][i] = 0.f;
    }
    if (i < NTILES) g_pcnt[i] = 0u;
    if (i < NSPLIT) g_scnt[i] = 0u;
}

// ---------------- P = x[:, :256, :] @ x2h ----------------
__global__ void p_kernel(const float* __restrict__ x, const float* __restrict__ x2h) {
    const int t  = blockIdx.x;
    const int n0 = blockIdx.y * 64;

    __shared__ __align__(16) float Xs[64 * 68];
    __shared__ __align__(16) float Ws[64 * 68];

    const int tid = threadIdx.x;
#pragma unroll
    for (int i = 0; i < 4; i++) {
        int idx4 = tid + i * 256;
        int b  = idx4 >> 4;
        int k4 = (idx4 & 15) * 4;
        const float4 v = *(const float4*)&x[(b * T_ + t) * NI_ + k4];
        Xs[(k4 + 0) * 68 + b] = v.x;
        Xs[(k4 + 1) * 68 + b] = v.y;
        Xs[(k4 + 2) * 68 + b] = v.z;
        Xs[(k4 + 3) * 68 + b] = v.w;
    }
#pragma unroll
    for (int i = 0; i < 4; i++) {
        int idx4 = tid + i * 256;
        int k  = idx4 >> 4;
        int n4 = (idx4 & 15) * 4;
        *(float4*)&Ws[k * 68 + n4] = *(const float4*)&x2h[k * H_ + n0 + n4];
    }
    __syncthreads();

    const int tx = tid & 15, ty = tid >> 4;
    float acc[4][4] = {};
#pragma unroll
    for (int k = 0; k < 64; k++) {
        const float4 a  = *(const float4*)&Xs[k * 68 + ty * 4];
        const float4 bb = *(const float4*)&Ws[k * 68 + tx * 4];
        acc[0][0] += a.x * bb.x; acc[0][1] += a.x * bb.y; acc[0][2] += a.x * bb.z; acc[0][3] += a.x * bb.w;
        acc[1][0] += a.y * bb.x; acc[1][1] += a.y * bb.y; acc[1][2] += a.y * bb.z; acc[1][3] += a.y * bb.w;
        acc[2][0] += a.z * bb.x; acc[2][1] += a.z * bb.y; acc[2][2] += a.z * bb.z; acc[2][3] += a.z * bb.w;
        acc[3][0] += a.w * bb.x; acc[3][1] += a.w * bb.y; acc[3][2] += a.w * bb.z; acc[3][3] += a.w * bb.w;
    }
#pragma unroll
    for (int i = 0; i < 4; i++) {
        int b = ty * 4 + i;
        *(float4*)&g_P[(t * 64 + b) * H_ + n0 + tx * 4] =
            make_float4(acc[i][0], acc[i][1], acc[i][2], acc[i][3]);
    }
}

// ---------------- persistent harmonic recurrence, point-to-point dataflow ----------------
// 128 CTAs: tile = blockIdx.x>>4 (N-tile of 128), split = blockIdx.x&15 (K-chunk of 64).
// No global barrier. Per step:
//   fill As (gated on own split-group's update, g_scnt[split] >= 8t)
//   GEMM (R10 FFMA2, bit-identical) -> partials g_Wp[t&1][split]
//   arrive g_pcnt[tile]
//   update own 8-row x 64-col block (gated on g_pcnt[split>>1] >= 16(t+1)); hz in regs
//   arrive g_scnt[split]
__global__ void __launch_bounds__(256, 1)
ron_kernel(const float* __restrict__ h2h,
           const float* __restrict__ bias,
           const float* __restrict__ gamma_,
           const float* __restrict__ eps_,
           float* __restrict__ out) {
    const int tile  = blockIdx.x >> 4;
    const int split = blockIdx.x & 15;
    const int n0 = tile * 128;
    const int k0 = split * 64;
    const int tid = threadIdx.x;
    const int tx = tid & 15, ty = tid >> 4;

    // As: m-major 64x64, XOR-swizzled 16B chunks: chunk(m,k) = (k>>2)^(m&15)
    __shared__ __align__(16) float As[64 * 64];     // 16 KB
    __shared__ __align__(16) float Bs[64 * 128];    // 32 KB

    // load h2h slice once (reused all 256 steps)
#pragma unroll
    for (int i = 0; i < 8; i++) {
        int idx4 = tid + i * 256;
        int k  = idx4 >> 5;
        int n4 = (idx4 & 31) * 4;
        *(float4*)&Bs[k * 128 + n4] = *(const float4*)&h2h[(k0 + k) * H_ + n0 + n4];
    }

    // ---- update-phase invariants: this thread owns (ub, uh..uh+1), fixed all steps ----
    const int ur = tid >> 5;                 // 0..7
    const int uc = (tid & 31) * 2;           // even local col in [0,64)
    const int ub = tile * 8 + ur;            // owned batch row
    const int uh = k0 + uc;                  // owned hidden col pair (== own As k-slice!)
    const int ug = ub * H_ + uh;
    // As float-index of (m=ub, k=uc) under swizzle (uc even -> float2 aligned)
    const int afi = ub * 64 + (((uc >> 2) ^ (ub & 15)) << 2) + (uc & 3);
    const float2 bv = *(const float2*)&bias[uh];
    const float2 gv = *(const float2*)&gamma_[uh];
    const float2 ev = *(const float2*)&eps_[uh];
    const int pt = split >> 1;               // tile whose partials feed our update
    float hz0 = 0.f, hz1 = 0.f;              // hz state in registers

    for (int t = 0; t <= THARM; t++) {
        // gate: our split-group finished writing hy[:, k0:k0+64) for step t
        if (t > 0) wait_ge(&g_scnt[split], 8u * (unsigned)t);

        const float* __restrict__ hy = g_hy[t & 1];
        // fill As with hy[m, k0:k0+64], swizzled (coalesced LDG, conflict-free STS.128)
#pragma unroll
        for (int i = 0; i < 4; i++) {
            int idx4 = tid + i * 256;
            int m  = idx4 >> 4;
            int k4 = (idx4 & 15) * 4;
            int c  = ((k4 >> 2) ^ (m & 15)) * 4;
            *(float4*)&As[m * 64 + c] = *(const float4*)&hy[m * H_ + k0 + k4];
        }
        __syncthreads();

        // ---- GEMM: 64m x 128n x 64k ; thread tile 4m x 8n, packed f32x2 (R10-identical) ----
        unsigned long long acc[4][4] = {};
#pragma unroll 4
        for (int kb = 0; kb < 16; kb++) {
            float4 av[4];
#pragma unroll
            for (int i = 0; i < 4; i++) {
                int m = ty * 4 + i;
                av[i] = *(const float4*)&As[m * 64 + ((kb ^ (m & 15)) << 2)];
            }
#pragma unroll
            for (int j = 0; j < 4; j++) {
                const int k = kb * 4 + j;
                const ulonglong2 q0 = *(const ulonglong2*)&Bs[k * 128 + tx * 4];
                const ulonglong2 q1 = *(const ulonglong2*)&Bs[k * 128 + 64 + tx * 4];
                float a0 = (j == 0) ? av[0].x : (j == 1) ? av[0].y : (j == 2) ? av[0].z : av[0].w;
                float a1 = (j == 0) ? av[1].x : (j == 1) ? av[1].y : (j == 2) ? av[1].z : av[1].w;
                float a2 = (j == 0) ? av[2].x : (j == 1) ? av[2].y : (j == 2) ? av[2].z : av[2].w;
                float a3 = (j == 0) ? av[3].x : (j == 1) ? av[3].y : (j == 2) ? av[3].z : av[3].w;
                unsigned long long d0 = dupf(a0), d1 = dupf(a1), d2 = dupf(a2), d3 = dupf(a3);
                fma2(acc[0][0], d0, q0.x); fma2(acc[0][1], d0, q0.y); fma2(acc[0][2], d0, q1.x); fma2(acc[0][3], d0, q1.y);
                fma2(acc[1][0], d1, q0.x); fma2(acc[1][1], d1, q0.y); fma2(acc[1][2], d1, q1.x); fma2(acc[1][3], d1, q1.y);
                fma2(acc[2][0], d2, q0.x); fma2(acc[2][1], d2, q0.y); fma2(acc[2][2], d2, q1.x); fma2(acc[2][3], d2, q1.y);
                fma2(acc[3][0], d3, q0.x); fma2(acc[3][1], d3, q0.y); fma2(acc[3][2], d3, q1.x); fma2(acc[3][3], d3, q1.y);
            }
        }

        // store split-K partials (parity slot -> deterministic reduction, WAR-safe)
        float* __restrict__ wp = g_Wp[t & 1][split];
#pragma unroll
        for (int i = 0; i < 4; i++) {
            int m = ty * 4 + i;
            float2 p0 = unpk(acc[i][0]), p1 = unpk(acc[i][1]);
            float2 p2 = unpk(acc[i][2]), p3 = unpk(acc[i][3]);
            *(float4*)&wp[m * H_ + n0 + tx * 4]      = make_float4(p0.x, p0.y, p1.x, p1.y);
            *(float4*)&wp[m * H_ + n0 + 64 + tx * 4] = make_float4(p2.x, p2.y, p3.x, p3.y);
        }

        arrive(&g_pcnt[tile]);   // partials for N-tile `tile`, step t published

        if (t == THARM) break;   // final hyW: partials consumed by spike_kernel

        // preload operands independent of partials (overlap with wait)
        const float2 pv = *(const float2*)&g_P[t * BH + ug];
        float2 hyv = *(const float2*)&As[afi];      // own hy pair, from own smem

        // gate: all 16 partial slots covering our columns are published
        wait_ge(&g_pcnt[pt], 16u * (unsigned)(t + 1));

        // ---- owned-block ODE update (8 rows x 64 cols; 1 float2/thread) ----
        {
            const float* __restrict__ wb = &g_Wp[t & 1][0][ug];
            float2 w = *(const float2*)wb;
#pragma unroll
            for (int s = 1; s < NSPLIT; s++) {
                const float2 ws = *(const float2*)(wb + s * BH);
                w.x += ws.x; w.y += ws.y;
            }

            float2 hz2, hy2;
            hz2.x = hz0 + DTF * (tanhf(pv.x + w.x + bv.x) - gv.x * hyv.x - ev.x * hz0);
            hz2.y = hz1 + DTF * (tanhf(pv.y + w.y + bv.y) - gv.y * hyv.y - ev.y * hz1);
            hy2.x = hyv.x + DTF * hz2.x;
            hy2.y = hyv.y + DTF * hz2.y;
            hz0 = hz2.x; hz1 = hz2.y;

            *(float2*)&g_hy[(t & 1) ^ 1][ug] = hy2;

            const int o = (ub * T_ + t) * H_ + uh;
            *(float2*)&out[o]           = hy2;
            *(float2*)&out[OFF_HZS + o] = hz2;

            if (t == THARM - 1)                    // snapshot hz for tail_kernel
                *(float2*)&g_hzF[ug] = hz2;
        }

        arrive(&g_scnt[split]);  // hy slice [*, k0:k0+64) for step t+1 published
    }
}

// ---------------- broadcast tails: hys/hzs[:,256:,:] = final state ----------------
__global__ void tail_kernel(float* __restrict__ out) {
    int idx = blockIdx.x * blockDim.x + threadIdx.x;
    int e = idx * 4;
    int h = e & 1023;
    int t = (e >> 10) & 255;
    int b = e >> 18;
    const float4 hyv = *(const float4*)&g_hy[0][b * H_ + h];
    const float4 hzv = *(const float4*)&g_hzF[b * H_ + h];
    const int o = (b * T_ + 256 + t) * H_ + h;
    *(float4*)&out[o]           = hyv;
    *(float4*)&out[OFF_HZS + o] = hzv;
}

// ---------------- spiking phase: per-(b,h) sequential LIF chain ----------------
__global__ void spike_kernel(float* __restrict__ out) {
    const int g = blockIdx.x * blockDim.x + threadIdx.x;
    const int b = g >> 10;
    const int h = g & 1023;

    float hyW = 0.f;
#pragma unroll
    for (int s = 0; s < NSPLIT; s++) hyW += g_Wp[0][s][g];   // t=256 partials: parity 0

    float* __restrict__ us = out + OFF_US;
    float* __restrict__ sp = out + OFF_SPK;
    const float* __restrict__ Pp = g_P + g;
    const int ob = (b * TSPK) * H_ + h;

    float u = 0.f;
#pragma unroll 4
    for (int t = 0; t < TSPK; t++) {
        const float pt = Pp[t * (B_ * H_)];
        const float s = (u > THRESH) ? 1.f : 0.f;
        if (u > THRESH) u = RESETV;
        u = u + ((-u + hyW + pt) * 0.025f) * 0.042f;
        us[ob + t * H_] = u;
        sp[ob + t * H_] = s;
    }
}

// ---------------- launch ----------------
extern "C" void kernel_launch(void* const* d_in, const int* in_sizes, int n_in,
                              void* d_out, int out_size) {
    const float* x    = (const float*)d_in[0];
    const float* x2h  = (const float*)d_in[1];
    const float* h2h  = (const float*)d_in[2];
    const float* bias = (const float*)d_in[3];
    const float* gam  = (const float*)d_in[4];
    const float* eps  = (const float*)d_in[5];
    float* out = (float*)d_out;
    (void)in_sizes; (void)n_in; (void)out_size;

    init_kernel<<<(B_ * H_ + 255) / 256, 256>>>();
    p_kernel<<<dim3(THARM, H_ / 64), 256>>>(x, x2h);
    ron_kernel<<<GRID, 256>>>(h2h, bias, gam, eps, out);
    tail_kernel<<<(B_ * TSPK * H_ / 4 + 255) / 256, 256>>>(out);
    spike_kernel<<<(B_ * H_ + 255) / 256, 256>>>(out);
}